// round 16
// baseline (speedup 1.0000x reference)
#include <cuda_runtime.h>
#include <math.h>

#define T_  2048
#define B_  2
#define C_  1024
#define H_  16
#define DK_ 64
#define BH_ (B_*H_)

// ---------------- scratch (device globals — no allocation allowed) ----------
__device__ float g_qr[B_*T_*C_];     // roped q, [B*T, C] row-major (m = b*T+t)
__device__ float g_kr[B_*T_*C_];
__device__ float g_vr[B_*T_*C_];
__device__ float g_Q [B_*T_*C_];     // projected, [B,T,H,DK] == [B*T, C]
__device__ float g_K [B_*T_*C_];
__device__ float g_V [B_*T_*C_];
__device__ float g_X [B_*T_*C_];     // attention output, [B,T,H,DK]
__device__ float g_S [(size_t)BH_*T_*T_];   // scores / probs, 512 MB
__device__ float g_cos[T_*(DK_/2)];
__device__ float g_sin[T_*(DK_/2)];

// ---------------- RoPE tables (mirror reference fp32 formula) ---------------
__global__ void rope_table_kernel() {
    int idx = blockIdx.x * blockDim.x + threadIdx.x;   // T_*32
    if (idx >= T_ * (DK_/2)) return;
    int i = idx & 31;
    int t = idx >> 5;
    // inv_freq = 1 / 10000^(2i/64)
    float inv = powf(10000.0f, -((float)(2*i) / (float)DK_));
    float ang = (float)t * inv;
    g_cos[idx] = cosf(ang);
    g_sin[idx] = sinf(ang);
}

// ---------------- RoPE + [T,B,C] -> [B*T, C] reorder -----------------------
__global__ void rope_reorder_kernel(const float* __restrict__ q,
                                    const float* __restrict__ k,
                                    const float* __restrict__ v) {
    int idx = blockIdx.x * blockDim.x + threadIdx.x;   // T*B*C
    if (idx >= T_*B_*C_) return;
    int c  = idx % C_;
    int tb = idx / C_;
    int b  = tb % B_;
    int t  = tb / B_;
    int d  = c & (DK_-1);
    int i  = d & 31;
    float cs = g_cos[t*32 + i];
    float sn = g_sin[t*32 + i];
    float qv = q[idx], kv = k[idx];
    float qrot = (d < 32) ? -q[idx + 32] : q[idx - 32];
    float krot = (d < 32) ? -k[idx + 32] : k[idx - 32];
    size_t o = (size_t)(b*T_ + t) * C_ + c;
    g_qr[o] = qv*cs + qrot*sn;
    g_kr[o] = kv*cs + krot*sn;
    g_vr[o] = v[idx];
}

// ---------------- generic NT GEMM: C[m,n] = alpha*sum_k A[m,k]*B[n,k] (+bias)
// Batched over blockIdx.z with (z/H, z%H) double strides.
// outMode 1: store to out[(t*B + b)*ldc + n] with m = b*T + t (final transpose).
__global__ __launch_bounds__(256)
void gemm_nt_kernel(const float* __restrict__ A, int lda, long aZb, long aZh,
                    const float* __restrict__ Bm, int ldb, long bZb, long bZh,
                    const float* __restrict__ bias,
                    float* __restrict__ Cc, int ldc, long cZb, long cZh,
                    int K, float alpha, int outMode)
{
    int z  = blockIdx.z;
    int zb = z / H_, zh = z % H_;
    A  += (size_t)zb*aZb + (size_t)zh*aZh;
    Bm += (size_t)zb*bZb + (size_t)zh*bZh;
    Cc += (size_t)zb*cZb + (size_t)zh*cZh;

    __shared__ float As[64][17];    // [m][k], padded: conflict-light
    __shared__ float Bs[16][68];    // [k][n], 272B row stride (16B aligned)

    int tid = threadIdx.x;
    int tx = tid & 15, ty = tid >> 4;
    int lr = tid >> 2;              // 0..63
    int lc = (tid & 3) * 4;         // 0,4,8,12

    int bm = blockIdx.y * 64;
    int bn = blockIdx.x * 64;

    float acc[4][4] = {};

    for (int k0 = 0; k0 < K; k0 += 16) {
        float4 av = *reinterpret_cast<const float4*>(&A[(size_t)(bm + lr)*lda + k0 + lc]);
        As[lr][lc+0] = av.x; As[lr][lc+1] = av.y;
        As[lr][lc+2] = av.z; As[lr][lc+3] = av.w;
        float4 bv = *reinterpret_cast<const float4*>(&Bm[(size_t)(bn + lr)*ldb + k0 + lc]);
        Bs[lc+0][lr] = bv.x; Bs[lc+1][lr] = bv.y;
        Bs[lc+2][lr] = bv.z; Bs[lc+3][lr] = bv.w;
        __syncthreads();
        #pragma unroll
        for (int kk = 0; kk < 16; ++kk) {
            float a0 = As[ty*4+0][kk], a1 = As[ty*4+1][kk];
            float a2 = As[ty*4+2][kk], a3 = As[ty*4+3][kk];
            float4 b4 = *reinterpret_cast<const float4*>(&Bs[kk][tx*4]);
            acc[0][0] += a0*b4.x; acc[0][1] += a0*b4.y; acc[0][2] += a0*b4.z; acc[0][3] += a0*b4.w;
            acc[1][0] += a1*b4.x; acc[1][1] += a1*b4.y; acc[1][2] += a1*b4.z; acc[1][3] += a1*b4.w;
            acc[2][0] += a2*b4.x; acc[2][1] += a2*b4.y; acc[2][2] += a2*b4.z; acc[2][3] += a2*b4.w;
            acc[3][0] += a3*b4.x; acc[3][1] += a3*b4.y; acc[3][2] += a3*b4.z; acc[3][3] += a3*b4.w;
        }
        __syncthreads();
    }

    #pragma unroll
    for (int i = 0; i < 4; ++i) {
        int m = bm + ty*4 + i;
        #pragma unroll
        for (int j = 0; j < 4; ++j) {
            int n = bn + tx*4 + j;
            float v = acc[i][j] * alpha + (bias ? bias[n] : 0.0f);
            if (outMode == 0) {
                Cc[(size_t)m*ldc + n] = v;
            } else {
                int tt = m % T_, bb = m / T_;
                Cc[(size_t)(tt*B_ + bb)*ldc + n] = v;
            }
        }
    }
}

// ---------------- row softmax over last dim (len 2048), in place ------------
__global__ __launch_bounds__(256)
void softmax_kernel() {
    size_t row = blockIdx.x;
    float* r = g_S + row * (size_t)T_;
    int tid = threadIdx.x;
    float vals[8];
    float mx = -INFINITY;
    #pragma unroll
    for (int j = 0; j < 8; ++j) { vals[j] = r[tid + j*256]; mx = fmaxf(mx, vals[j]); }
    __shared__ float red[256];
    red[tid] = mx; __syncthreads();
    for (int s = 128; s > 0; s >>= 1) { if (tid < s) red[tid] = fmaxf(red[tid], red[tid+s]); __syncthreads(); }
    mx = red[0]; __syncthreads();
    float sum = 0.0f;
    #pragma unroll
    for (int j = 0; j < 8; ++j) { vals[j] = __expf(vals[j] - mx); sum += vals[j]; }
    red[tid] = sum; __syncthreads();
    for (int s = 128; s > 0; s >>= 1) { if (tid < s) red[tid] += red[tid+s]; __syncthreads(); }
    float inv = 1.0f / red[0];
    #pragma unroll
    for (int j = 0; j < 8; ++j) r[tid + j*256] = vals[j] * inv;
}

// ---------------- PV: X[m,n] = sum_k P[m,k]*V[k,n] per (b,h) ----------------
__global__ __launch_bounds__(256)
void gemm_pv_kernel() {
    int z = blockIdx.z;
    int b = z / H_, h = z % H_;
    const float* P  = g_S + (size_t)z * T_ * T_;
    const float* Vb = g_V + (size_t)b*T_*C_ + h*DK_;   // V[k][n] @ Vb[k*C_ + n]
    float*       Xb = g_X + (size_t)b*T_*C_ + h*DK_;   // X[m][n] @ Xb[m*C_ + n]

    __shared__ float Ps[64][17];
    __shared__ float Vs[16][64];

    int tid = threadIdx.x;
    int tx = tid & 15, ty = tid >> 4;
    int lr = tid >> 2, lc = (tid & 3) * 4;
    int vn = tid & 63, vk = tid >> 6;      // vk 0..3
    int bm = blockIdx.y * 64;

    float acc[4][4] = {};

    for (int k0 = 0; k0 < T_; k0 += 16) {
        float4 pv4 = *reinterpret_cast<const float4*>(&P[(size_t)(bm + lr)*T_ + k0 + lc]);
        Ps[lr][lc+0] = pv4.x; Ps[lr][lc+1] = pv4.y;
        Ps[lr][lc+2] = pv4.z; Ps[lr][lc+3] = pv4.w;
        #pragma unroll
        for (int p = 0; p < 4; ++p) {
            int kk = vk + p*4;
            Vs[kk][vn] = Vb[(size_t)(k0 + kk)*C_ + vn];
        }
        __syncthreads();
        #pragma unroll
        for (int kk = 0; kk < 16; ++kk) {
            float a0 = Ps[ty*4+0][kk], a1 = Ps[ty*4+1][kk];
            float a2 = Ps[ty*4+2][kk], a3 = Ps[ty*4+3][kk];
            float4 b4 = *reinterpret_cast<const float4*>(&Vs[kk][tx*4]);
            acc[0][0] += a0*b4.x; acc[0][1] += a0*b4.y; acc[0][2] += a0*b4.z; acc[0][3] += a0*b4.w;
            acc[1][0] += a1*b4.x; acc[1][1] += a1*b4.y; acc[1][2] += a1*b4.z; acc[1][3] += a1*b4.w;
            acc[2][0] += a2*b4.x; acc[2][1] += a2*b4.y; acc[2][2] += a2*b4.z; acc[2][3] += a2*b4.w;
            acc[3][0] += a3*b4.x; acc[3][1] += a3*b4.y; acc[3][2] += a3*b4.z; acc[3][3] += a3*b4.w;
        }
        __syncthreads();
    }

    #pragma unroll
    for (int i = 0; i < 4; ++i)
        #pragma unroll
        for (int j = 0; j < 4; ++j)
            Xb[(size_t)(bm + ty*4 + i)*C_ + tx*4 + j] = acc[i][j];
}

// ---------------- host-side launch ------------------------------------------
extern "C" void kernel_launch(void* const* d_in, const int* in_sizes, int n_in,
                              void* d_out, int out_size) {
    const float* query = (const float*)d_in[0];
    const float* key   = (const float*)d_in[1];
    const float* value = (const float*)d_in[2];
    const float* Wq = (const float*)d_in[3];
    const float* bq = (const float*)d_in[4];
    const float* Wk = (const float*)d_in[5];
    const float* bk = (const float*)d_in[6];
    const float* Wv = (const float*)d_in[7];
    const float* bv = (const float*)d_in[8];
    const float* Wo = (const float*)d_in[9];
    const float* bo = (const float*)d_in[10];
    float* out = (float*)d_out;

    static float *p_qr = nullptr, *p_kr, *p_vr, *p_Q, *p_K, *p_V, *p_X, *p_S;
    if (!p_qr) {
        cudaGetSymbolAddress((void**)&p_qr, g_qr);
        cudaGetSymbolAddress((void**)&p_kr, g_kr);
        cudaGetSymbolAddress((void**)&p_vr, g_vr);
        cudaGetSymbolAddress((void**)&p_Q,  g_Q);
        cudaGetSymbolAddress((void**)&p_K,  g_K);
        cudaGetSymbolAddress((void**)&p_V,  g_V);
        cudaGetSymbolAddress((void**)&p_X,  g_X);
        cudaGetSymbolAddress((void**)&p_S,  g_S);
    }

    const float scale = 0.125f;   // 1/sqrt(64)

    // 1. RoPE tables
    rope_table_kernel<<<(T_*32 + 255)/256, 256>>>();
    // 2. RoPE + reorder to [B*T, C]
    rope_reorder_kernel<<<(T_*B_*C_)/256, 256>>>(query, key, value);

    // 3. Projections: [4096,1024] x [1024,1024]^T -> [B,T,H,DK]
    dim3 gProj(C_/64, (B_*T_)/64, 1);
    gemm_nt_kernel<<<gProj, 256>>>(p_qr, C_, 0, 0, Wq, C_, 0, 0, bq, p_Q, C_, 0, 0, C_, 1.0f, 0);
    gemm_nt_kernel<<<gProj, 256>>>(p_kr, C_, 0, 0, Wk, C_, 0, 0, bk, p_K, C_, 0, 0, C_, 1.0f, 0);
    gemm_nt_kernel<<<gProj, 256>>>(p_vr, C_, 0, 0, Wv, C_, 0, 0, bv, p_V, C_, 0, 0, C_, 1.0f, 0);

    // 4. Scores: per (b,h): S = scale * Q K^T   [2048 x 2048], K-dim 64
    dim3 gScores(T_/64, T_/64, BH_);
    gemm_nt_kernel<<<gScores, 256>>>(
        p_Q, C_, (long)T_*C_, DK_,
        p_K, C_, (long)T_*C_, DK_,
        nullptr,
        p_S, T_, (long)H_*T_*T_, (long)T_*T_,
        DK_, scale, 0);

    // 5. Softmax over rows (65536 rows x 2048)
    softmax_kernel<<<BH_*T_, 256>>>();

    // 6. PV: X = P @ V  -> [B,T,H,DK]
    dim3 gPV(1, T_/64, BH_);
    gemm_pv_kernel<<<gPV, 256>>>();

    // 7. Output projection with fused [B,T]->[T,B] transpose on store
    gemm_nt_kernel<<<gProj, 256>>>(p_X, C_, 0, 0, Wo, C_, 0, 0, bo, out, C_, 0, 0, C_, 1.0f, 1);
}

// round 17
// speedup vs baseline: 1.0014x; 1.0014x over previous
#include <cuda_runtime.h>
#include <math.h>

#define T_  2048
#define B_  2
#define C_  1024
#define H_  16
#define DK_ 64
#define BH_ (B_*H_)

// ---------------- scratch (device globals — no allocation allowed) ----------
__device__ float g_qr[B_*T_*C_];     // roped q, [B*T, C] row-major (m = b*T+t)
__device__ float g_kr[B_*T_*C_];
__device__ float g_vr[B_*T_*C_];
__device__ float g_Q [B_*T_*C_];     // projected, [B,T,H,DK] == [B*T, C]
__device__ float g_K [B_*T_*C_];
__device__ float g_V [B_*T_*C_];
__device__ float g_X [B_*T_*C_];     // attention output, [B,T,H,DK]
__device__ float g_S [(size_t)BH_*T_*T_];   // scores / probs, 512 MB
__device__ float g_cos[T_*(DK_/2)];
__device__ float g_sin[T_*(DK_/2)];

// ---------------- RoPE tables (mirror reference fp32 formula) ---------------
__global__ void rope_table_kernel() {
    int idx = blockIdx.x * blockDim.x + threadIdx.x;   // T_*32
    if (idx >= T_ * (DK_/2)) return;
    int i = idx & 31;
    int t = idx >> 5;
    // inv_freq = 1 / 10000^(2i/64)
    float inv = powf(10000.0f, -((float)(2*i) / (float)DK_));
    float ang = (float)t * inv;
    g_cos[idx] = cosf(ang);
    g_sin[idx] = sinf(ang);
}

// ---------------- RoPE + [T,B,C] -> [B*T, C] reorder -----------------------
__global__ void rope_reorder_kernel(const float* __restrict__ q,
                                    const float* __restrict__ k,
                                    const float* __restrict__ v) {
    int idx = blockIdx.x * blockDim.x + threadIdx.x;   // T*B*C
    if (idx >= T_*B_*C_) return;
    int c  = idx % C_;
    int tb = idx / C_;
    int b  = tb % B_;
    int t  = tb / B_;
    int d  = c & (DK_-1);
    int i  = d & 31;
    float cs = g_cos[t*32 + i];
    float sn = g_sin[t*32 + i];
    float qv = q[idx], kv = k[idx];
    float qrot = (d < 32) ? -q[idx + 32] : q[idx - 32];
    float krot = (d < 32) ? -k[idx + 32] : k[idx - 32];
    size_t o = (size_t)(b*T_ + t) * C_ + c;
    g_qr[o] = qv*cs + qrot*sn;
    g_kr[o] = kv*cs + krot*sn;
    g_vr[o] = v[idx];
}

// ---------------- generic NT GEMM: C[m,n] = alpha*sum_k A[m,k]*B[n,k] (+bias)
// Batched over blockIdx.z with (z/H, z%H) double strides.
// outMode 1: store to out[(t*B + b)*ldc + n] with m = b*T + t (final transpose).
__global__ __launch_bounds__(256)
void gemm_nt_kernel(const float* __restrict__ A, int lda, long aZb, long aZh,
                    const float* __restrict__ Bm, int ldb, long bZb, long bZh,
                    const float* __restrict__ bias,
                    float* __restrict__ Cc, int ldc, long cZb, long cZh,
                    int K, float alpha, int outMode)
{
    int z  = blockIdx.z;
    int zb = z / H_, zh = z % H_;
    A  += (size_t)zb*aZb + (size_t)zh*aZh;
    Bm += (size_t)zb*bZb + (size_t)zh*bZh;
    Cc += (size_t)zb*cZb + (size_t)zh*cZh;

    __shared__ float As[64][17];    // [m][k], padded: conflict-light
    __shared__ float Bs[16][68];    // [k][n], 272B row stride (16B aligned)

    int tid = threadIdx.x;
    int tx = tid & 15, ty = tid >> 4;
    int lr = tid >> 2;              // 0..63
    int lc = (tid & 3) * 4;         // 0,4,8,12

    int bm = blockIdx.y * 64;
    int bn = blockIdx.x * 64;

    float acc[4][4] = {};

    for (int k0 = 0; k0 < K; k0 += 16) {
        float4 av = *reinterpret_cast<const float4*>(&A[(size_t)(bm + lr)*lda + k0 + lc]);
        As[lr][lc+0] = av.x; As[lr][lc+1] = av.y;
        As[lr][lc+2] = av.z; As[lr][lc+3] = av.w;
        float4 bv = *reinterpret_cast<const float4*>(&Bm[(size_t)(bn + lr)*ldb + k0 + lc]);
        Bs[lc+0][lr] = bv.x; Bs[lc+1][lr] = bv.y;
        Bs[lc+2][lr] = bv.z; Bs[lc+3][lr] = bv.w;
        __syncthreads();
        #pragma unroll
        for (int kk = 0; kk < 16; ++kk) {
            float a0 = As[ty*4+0][kk], a1 = As[ty*4+1][kk];
            float a2 = As[ty*4+2][kk], a3 = As[ty*4+3][kk];
            float4 b4 = *reinterpret_cast<const float4*>(&Bs[kk][tx*4]);
            acc[0][0] += a0*b4.x; acc[0][1] += a0*b4.y; acc[0][2] += a0*b4.z; acc[0][3] += a0*b4.w;
            acc[1][0] += a1*b4.x; acc[1][1] += a1*b4.y; acc[1][2] += a1*b4.z; acc[1][3] += a1*b4.w;
            acc[2][0] += a2*b4.x; acc[2][1] += a2*b4.y; acc[2][2] += a2*b4.z; acc[2][3] += a2*b4.w;
            acc[3][0] += a3*b4.x; acc[3][1] += a3*b4.y; acc[3][2] += a3*b4.z; acc[3][3] += a3*b4.w;
        }
        __syncthreads();
    }

    #pragma unroll
    for (int i = 0; i < 4; ++i) {
        int m = bm + ty*4 + i;
        #pragma unroll
        for (int j = 0; j < 4; ++j) {
            int n = bn + tx*4 + j;
            float v = acc[i][j] * alpha + (bias ? bias[n] : 0.0f);
            if (outMode == 0) {
                Cc[(size_t)m*ldc + n] = v;
            } else {
                int tt = m % T_, bb = m / T_;
                Cc[(size_t)(tt*B_ + bb)*ldc + n] = v;
            }
        }
    }
}

// ---------------- row softmax over last dim (len 2048), in place ------------
__global__ __launch_bounds__(256)
void softmax_kernel() {
    size_t row = blockIdx.x;
    float* r = g_S + row * (size_t)T_;
    int tid = threadIdx.x;
    float vals[8];
    float mx = -INFINITY;
    #pragma unroll
    for (int j = 0; j < 8; ++j) { vals[j] = r[tid + j*256]; mx = fmaxf(mx, vals[j]); }
    __shared__ float red[256];
    red[tid] = mx; __syncthreads();
    for (int s = 128; s > 0; s >>= 1) { if (tid < s) red[tid] = fmaxf(red[tid], red[tid+s]); __syncthreads(); }
    mx = red[0]; __syncthreads();
    float sum = 0.0f;
    #pragma unroll
    for (int j = 0; j < 8; ++j) { vals[j] = __expf(vals[j] - mx); sum += vals[j]; }
    red[tid] = sum; __syncthreads();
    for (int s = 128; s > 0; s >>= 1) { if (tid < s) red[tid] += red[tid+s]; __syncthreads(); }
    float inv = 1.0f / red[0];
    #pragma unroll
    for (int j = 0; j < 8; ++j) r[tid + j*256] = vals[j] * inv;
}

// ---------------- PV: X[m,n] = sum_k P[m,k]*V[k,n] per (b,h) ----------------
__global__ __launch_bounds__(256)
void gemm_pv_kernel() {
    int z = blockIdx.z;
    int b = z / H_, h = z % H_;
    const float* P  = g_S + (size_t)z * T_ * T_;
    const float* Vb = g_V + (size_t)b*T_*C_ + h*DK_;   // V[k][n] @ Vb[k*C_ + n]
    float*       Xb = g_X + (size_t)b*T_*C_ + h*DK_;   // X[m][n] @ Xb[m*C_ + n]

    __shared__ float Ps[64][17];
    __shared__ float Vs[16][64];

    int tid = threadIdx.x;
    int tx = tid & 15, ty = tid >> 4;
    int lr = tid >> 2, lc = (tid & 3) * 4;
    int vn = tid & 63, vk = tid >> 6;      // vk 0..3
    int bm = blockIdx.y * 64;

    float acc[4][4] = {};

    for (int k0 = 0; k0 < T_; k0 += 16) {
        float4 pv4 = *reinterpret_cast<const float4*>(&P[(size_t)(bm + lr)*T_ + k0 + lc]);
        Ps[lr][lc+0] = pv4.x; Ps[lr][lc+1] = pv4.y;
        Ps[lr][lc+2] = pv4.z; Ps[lr][lc+3] = pv4.w;
        #pragma unroll
        for (int p = 0; p < 4; ++p) {
            int kk = vk + p*4;
            Vs[kk][vn] = Vb[(size_t)(k0 + kk)*C_ + vn];
        }
        __syncthreads();
        #pragma unroll
        for (int kk = 0; kk < 16; ++kk) {
            float a0 = Ps[ty*4+0][kk], a1 = Ps[ty*4+1][kk];
            float a2 = Ps[ty*4+2][kk], a3 = Ps[ty*4+3][kk];
            float4 b4 = *reinterpret_cast<const float4*>(&Vs[kk][tx*4]);
            acc[0][0] += a0*b4.x; acc[0][1] += a0*b4.y; acc[0][2] += a0*b4.z; acc[0][3] += a0*b4.w;
            acc[1][0] += a1*b4.x; acc[1][1] += a1*b4.y; acc[1][2] += a1*b4.z; acc[1][3] += a1*b4.w;
            acc[2][0] += a2*b4.x; acc[2][1] += a2*b4.y; acc[2][2] += a2*b4.z; acc[2][3] += a2*b4.w;
            acc[3][0] += a3*b4.x; acc[3][1] += a3*b4.y; acc[3][2] += a3*b4.z; acc[3][3] += a3*b4.w;
        }
        __syncthreads();
    }

    #pragma unroll
    for (int i = 0; i < 4; ++i)
        #pragma unroll
        for (int j = 0; j < 4; ++j)
            Xb[(size_t)(bm + ty*4 + i)*C_ + tx*4 + j] = acc[i][j];
}

// ---------------- host-side launch ------------------------------------------
extern "C" void kernel_launch(void* const* d_in, const int* in_sizes, int n_in,
                              void* d_out, int out_size) {
    const float* query = (const float*)d_in[0];
    const float* key   = (const float*)d_in[1];
    const float* value = (const float*)d_in[2];
    const float* Wq = (const float*)d_in[3];
    const float* bq = (const float*)d_in[4];
    const float* Wk = (const float*)d_in[5];
    const float* bk = (const float*)d_in[6];
    const float* Wv = (const float*)d_in[7];
    const float* bv = (const float*)d_in[8];
    const float* Wo = (const float*)d_in[9];
    const float* bo = (const float*)d_in[10];
    float* out = (float*)d_out;

    static float *p_qr = nullptr, *p_kr, *p_vr, *p_Q, *p_K, *p_V, *p_X, *p_S;
    if (!p_qr) {
        cudaGetSymbolAddress((void**)&p_qr, g_qr);
        cudaGetSymbolAddress((void**)&p_kr, g_kr);
        cudaGetSymbolAddress((void**)&p_vr, g_vr);
        cudaGetSymbolAddress((void**)&p_Q,  g_Q);
        cudaGetSymbolAddress((void**)&p_K,  g_K);
        cudaGetSymbolAddress((void**)&p_V,  g_V);
        cudaGetSymbolAddress((void**)&p_X,  g_X);
        cudaGetSymbolAddress((void**)&p_S,  g_S);
    }

    const float scale = 0.125f;   // 1/sqrt(64)

    // 1. RoPE tables
    rope_table_kernel<<<(T_*32 + 255)/256, 256>>>();
    // 2. RoPE + reorder to [B*T, C]
    rope_reorder_kernel<<<(T_*B_*C_)/256, 256>>>(query, key, value);

    // 3. Projections: [4096,1024] x [1024,1024]^T -> [B,T,H,DK]
    dim3 gProj(C_/64, (B_*T_)/64, 1);
    gemm_nt_kernel<<<gProj, 256>>>(p_qr, C_, 0, 0, Wq, C_, 0, 0, bq, p_Q, C_, 0, 0, C_, 1.0f, 0);
    gemm_nt_kernel<<<gProj, 256>>>(p_kr, C_, 0, 0, Wk, C_, 0, 0, bk, p_K, C_, 0, 0, C_, 1.0f, 0);
    gemm_nt_kernel<<<gProj, 256>>>(p_vr, C_, 0, 0, Wv, C_, 0, 0, bv, p_V, C_, 0, 0, C_, 1.0f, 0);

    // 4. Scores: per (b,h): S = scale * Q K^T   [2048 x 2048], K-dim 64
    dim3 gScores(T_/64, T_/64, BH_);
    gemm_nt_kernel<<<gScores, 256>>>(
        p_Q, C_, (long)T_*C_, DK_,
        p_K, C_, (long)T_*C_, DK_,
        nullptr,
        p_S, T_, (long)H_*T_*T_, (long)T_*T_,
        DK_, scale, 0);

    // 5. Softmax over rows (65536 rows x 2048)
    softmax_kernel<<<BH_*T_, 256>>>();

    // 6. PV: X = P @ V  -> [B,T,H,DK]
    dim3 gPV(1, T_/64, BH_);
    gemm_pv_kernel<<<gPV, 256>>>();

    // 7. Output projection with fused [B,T]->[T,B] transpose on store
    gemm_nt_kernel<<<gProj, 256>>>(p_X, C_, 0, 0, Wo, C_, 0, 0, bo, out, C_, 0, 0, C_, 1.0f, 1);
}